// round 1
// baseline (speedup 1.0000x reference)
#include <cuda_runtime.h>

typedef unsigned long long ull;

__device__ __forceinline__ ull pack2(float lo, float hi){
    ull r; asm("mov.b64 %0, {%1, %2};" : "=l"(r) : "f"(lo), "f"(hi)); return r;
}
__device__ __forceinline__ void unpack2(ull v, float& lo, float& hi){
    asm("mov.b64 {%0, %1}, %2;" : "=f"(lo), "=f"(hi) : "l"(v));
}
__device__ __forceinline__ void fma2(ull& acc, ull a, ull b){
    asm("fma.rn.f32x2 %0, %1, %2, %0;" : "+l"(acc) : "l"(a), "l"(b));
}
__device__ __forceinline__ float leaky(float v){ return v > 0.f ? v : 0.01f*v; }

// ---------------- scratch (device globals; no runtime allocation) ----------------
__device__ float g_h[(size_t)2*64*94*94*94];   // c1 output (after leaky), 425 MB
__device__ float g_wc1[2*32*27*64];            // modulated c1 weights  [n][i][k][o]
__device__ float g_wc2[2*64*27*64];            // modulated c2 weights  [n][i][k][o]
__device__ float g_wskip[2*32*64];             // modulated skip weights [n][i][o]

// ---------------- prep: style MLP + weight modulation/demodulation ----------------
__global__ void prep_kernel(const float* __restrict__ s,
                            const float* __restrict__ w1, const float* __restrict__ b1,
                            const float* __restrict__ w2, const float* __restrict__ b2,
                            const float* __restrict__ w3, const float* __restrict__ b3,
                            const float* __restrict__ wc,
                            float* __restrict__ gw,
                            int H1, int H2, int ICn, int Kn)
{
    const int n   = blockIdx.x;
    const int tid = threadIdx.x;
    __shared__ float sv[64], a1[128], a2[128], mod[64], dem[64];
    if (tid < 64) sv[tid] = s[n*64 + tid];
    __syncthreads();
    if (tid < H1){
        float acc = b1[tid];
        for (int k = 0; k < 64; k++) acc += sv[k]*w1[tid*64 + k];
        a1[tid] = leaky(acc);
    }
    __syncthreads();
    if (tid < H2){
        float acc = b2[tid];
        for (int k = 0; k < H1; k++) acc += a1[k]*w2[tid*H1 + k];
        a2[tid] = leaky(acc);
    }
    __syncthreads();
    if (tid < ICn){
        float acc = b3[tid];
        for (int k = 0; k < H2; k++) acc += a2[k]*w3[tid*H2 + k];
        mod[tid] = acc;
    }
    __syncthreads();
    if (tid < 64){                 // per output channel: demod scalar
        float ssum = 0.f;
        for (int i = 0; i < ICn; i++){
            float m = mod[i];
            const float* wp = wc + (tid*ICn + i)*Kn;
            for (int k = 0; k < Kn; k++){ float t = wp[k]*m; ssum += t*t; }
        }
        dem[tid] = rsqrtf(ssum + 1e-8f);
    }
    __syncthreads();
    const int total = ICn*Kn*64;
    for (int e = tid; e < total; e += blockDim.x){
        int o = e & 63;
        int r = e >> 6;
        int k = r % Kn;
        int i = r / Kn;
        gw[n*total + e] = wc[(o*ICn + i)*Kn + k] * mod[i] * dem[o];
    }
}

// ---------------- output store helper ----------------
template<int OUTD>
__device__ __forceinline__ void store_row(float* __restrict__ out, int n, int oc,
                                          int oz, int oy, int gx0, const float* v)
{
    int base = ((n*64 + oc)*OUTD + oz)*OUTD*OUTD + oy*OUTD + gx0;
    if constexpr ((OUTD & 3) == 0){
        #pragma unroll
        for (int g = 0; g < 2; g++){
            if (gx0 + 4*g + 3 < OUTD)
                *(float4*)(out + base + 4*g) = make_float4(v[4*g], v[4*g+1], v[4*g+2], v[4*g+3]);
        }
    } else {
        #pragma unroll
        for (int g = 0; g < 4; g++){
            int xs = gx0 + 2*g;
            if (xs + 1 < OUTD)
                *(float2*)(out + base + 2*g) = make_float2(v[2*g], v[2*g+1]);
            else if (xs < OUTD)
                out[base + 2*g] = v[2*g];
        }
    }
}

// ---------------- direct 3x3x3 conv, packed f32x2 micro-kernel ----------------
// CTA: 64 oc x (4z x 4y x 16x) voxels, 256 threads.
// Thread: 8 oc (4 f32x2 pairs) x 8 consecutive-x voxels = 32 ull accumulators.
// Smem per ic-chunk(8): input halo tile [8][6][6][20] + weights [8][27][64].
template<int IC, int IND, int OUTD, bool FUSE_SKIP>
__global__ __launch_bounds__(256, 2)
void conv3d_kernel(const float* __restrict__ in,     // [2][IC][IND^3]
                   const float* __restrict__ wbuf,   // [2][IC][27][64]
                   const float* __restrict__ bias1,  // [64]
                   const float* __restrict__ xsrc,   // x, for fused skip
                   const float* __restrict__ wskip,  // [2][32][64]
                   const float* __restrict__ bias2,  // skip bias
                   float* __restrict__ out)          // [2][64][OUTD^3]
{
    constexpr int BZ = (OUTD + 3) / 4;
    extern __shared__ float smem[];
    float* s_in = smem;           // 8*6*6*20 = 5760 floats
    float* s_w  = smem + 5760;    // 8*27*64 = 13824 floats

    const int tid = threadIdx.x;
    const int ocg = tid & 7;          // 0..7 -> oc base
    const int vg  = tid >> 3;         // 0..31
    const int tz  = vg >> 3;          // 0..3
    const int ty  = (vg >> 1) & 3;    // 0..3
    const int xb  = (vg & 1) * 8;     // 0 or 8
    const int ob  = ocg * 8;

    const int bx = blockIdx.x, by = blockIdx.y;
    const int n  = blockIdx.z / BZ;
    const int bz = blockIdx.z % BZ;
    const int z0 = bz*4, y0 = by*4, x0c = bx*16;

    const float* inb = in + (size_t)n * IC * IND * IND * IND;

    ull acc[4][8];
    #pragma unroll
    for (int p = 0; p < 4; p++)
        #pragma unroll
        for (int v = 0; v < 8; v++) acc[p][v] = 0ull;

    #pragma unroll 1
    for (int ic0 = 0; ic0 < IC; ic0 += 8){
        __syncthreads();
        // cooperative load: input halo tile (zero-fill out of range)
        #pragma unroll 1
        for (int e = tid; e < 8*6*6*18; e += 256){
            int xx = e % 18; int t = e / 18;
            int yy = t % 6;  t /= 6;
            int zz = t % 6;  int ic = t / 6;
            int gz = z0 + zz, gy = y0 + yy, gx = x0c + xx;
            float v = 0.f;
            if (gz < IND && gy < IND && gx < IND)
                v = inb[((ic0 + ic)*IND + gz)*(IND*IND) + gy*IND + gx];
            s_in[((ic*6 + zz)*6 + yy)*20 + xx] = v;
        }
        // cooperative load: weight chunk (contiguous)
        {
            const float4* wsrc = (const float4*)(wbuf + ((size_t)n*IC + ic0)*27*64);
            float4* wdst = (float4*)s_w;
            #pragma unroll 1
            for (int e = tid; e < 8*27*16; e += 256) wdst[e] = wsrc[e];
        }
        __syncthreads();

        #pragma unroll 1
        for (int ic = 0; ic < 8; ic++){
            #pragma unroll
            for (int kz = 0; kz < 3; kz++){
                #pragma unroll
                for (int ky = 0; ky < 3; ky++){
                    const float* r = s_in + ((ic*6 + tz + kz)*6 + (ty + ky))*20 + xb;
                    float4 ra = *(const float4*)r;
                    float4 rb = *(const float4*)(r + 4);
                    float2 rc = *(const float2*)(r + 8);
                    ull dup[10];
                    dup[0] = pack2(ra.x, ra.x); dup[1] = pack2(ra.y, ra.y);
                    dup[2] = pack2(ra.z, ra.z); dup[3] = pack2(ra.w, ra.w);
                    dup[4] = pack2(rb.x, rb.x); dup[5] = pack2(rb.y, rb.y);
                    dup[6] = pack2(rb.z, rb.z); dup[7] = pack2(rb.w, rb.w);
                    dup[8] = pack2(rc.x, rc.x); dup[9] = pack2(rc.y, rc.y);
                    const float* wrow = s_w + ((ic*9 + kz*3 + ky)*3)*64 + ob;
                    #pragma unroll
                    for (int kx = 0; kx < 3; kx++){
                        const ull* wp = (const ull*)(wrow + kx*64);   // pairs (2o,2o+1), 8B aligned
                        ull w0 = wp[0], w1 = wp[1], w2 = wp[2], w3 = wp[3];
                        #pragma unroll
                        for (int v = 0; v < 8; v++){
                            ull d = dup[v + kx];
                            fma2(acc[0][v], w0, d);
                            fma2(acc[1][v], w1, d);
                            fma2(acc[2][v], w2, d);
                            fma2(acc[3][v], w3, d);
                        }
                    }
                }
            }
        }
    }

    if constexpr (FUSE_SKIP){
        // fused 1x1 skip conv on x at cropped coords (+2 offset)
        float* s_xs = smem;          // [32][4][4][16] = 8192 floats
        float* s_ws = smem + 8192;   // [32][64]       = 2048 floats
        __syncthreads();
        const float* xbatch = xsrc + (size_t)n * 32 * 96 * 96 * 96;
        #pragma unroll 1
        for (int e = tid; e < 8192; e += 256){
            int xx = e & 15, yy = (e >> 4) & 3, zz = (e >> 6) & 3, ic = e >> 8;
            int gz = z0 + 2 + zz, gy = y0 + 2 + yy, gx = x0c + 2 + xx;
            float v = 0.f;
            if (gz < 96 && gy < 96 && gx < 96)
                v = xbatch[(ic*96 + gz)*9216 + gy*96 + gx];
            s_xs[e] = v;
        }
        #pragma unroll 1
        for (int e = tid; e < 2048; e += 256)
            s_ws[e] = wskip[n*2048 + e];
        __syncthreads();

        #pragma unroll 1
        for (int ic = 0; ic < 32; ic++){
            const ull* wp = (const ull*)(s_ws + ic*64 + ob);
            ull w0 = wp[0], w1 = wp[1], w2 = wp[2], w3 = wp[3];
            const float* xr = s_xs + ic*256 + (tz*4 + ty)*16 + xb;
            float4 xa = *(const float4*)xr;
            float4 xv = *(const float4*)(xr + 4);
            float xin[8] = {xa.x, xa.y, xa.z, xa.w, xv.x, xv.y, xv.z, xv.w};
            #pragma unroll
            for (int v = 0; v < 8; v++){
                ull d = pack2(xin[v], xin[v]);
                fma2(acc[0][v], w0, d);
                fma2(acc[1][v], w1, d);
                fma2(acc[2][v], w2, d);
                fma2(acc[3][v], w3, d);
            }
        }
    }

    // epilogue: bias (+skip bias), leaky, vectorized store
    const int oz = z0 + tz, oy = y0 + ty;
    if (oz < OUTD && oy < OUTD){
        const int gx0 = x0c + xb;
        #pragma unroll
        for (int p = 0; p < 4; p++){
            const int oc0 = ob + 2*p;
            float b0 = bias1[oc0],     b1v = bias1[oc0 + 1];
            if constexpr (FUSE_SKIP){ b0 += bias2[oc0]; b1v += bias2[oc0 + 1]; }
            float lo[8], hi[8];
            #pragma unroll
            for (int v = 0; v < 8; v++){
                float a, b;
                unpack2(acc[p][v], a, b);
                lo[v] = leaky(a + b0);
                hi[v] = leaky(b + b1v);
            }
            store_row<OUTD>(out, n, oc0,     oz, oy, gx0, lo);
            store_row<OUTD>(out, n, oc0 + 1, oz, oy, gx0, hi);
        }
    }
}

// ---------------- launch ----------------
static const int SMEM_BYTES = (5760 + 13824) * 4;   // 78336

extern "C" void kernel_launch(void* const* d_in, const int* in_sizes, int n_in,
                              void* d_out, int out_size)
{
    (void)in_sizes; (void)n_in; (void)out_size;

    const float* x        = (const float*)d_in[0];
    const float* s        = (const float*)d_in[1];
    const float* skip_w1  = (const float*)d_in[2];
    const float* skip_b1  = (const float*)d_in[3];
    const float* skip_w2  = (const float*)d_in[4];
    const float* skip_b2  = (const float*)d_in[5];
    const float* skip_w3  = (const float*)d_in[6];
    const float* skip_b3  = (const float*)d_in[7];
    const float* skip_wc  = (const float*)d_in[8];
    const float* skip_bc  = (const float*)d_in[9];
    const float* c1_w1    = (const float*)d_in[10];
    const float* c1_b1    = (const float*)d_in[11];
    const float* c1_w2    = (const float*)d_in[12];
    const float* c1_b2    = (const float*)d_in[13];
    const float* c1_w3    = (const float*)d_in[14];
    const float* c1_b3    = (const float*)d_in[15];
    const float* c1_wc    = (const float*)d_in[16];
    const float* c1_bc    = (const float*)d_in[17];
    const float* c2_w1    = (const float*)d_in[18];
    const float* c2_b1    = (const float*)d_in[19];
    const float* c2_w2    = (const float*)d_in[20];
    const float* c2_b2    = (const float*)d_in[21];
    const float* c2_w3    = (const float*)d_in[22];
    const float* c2_b3    = (const float*)d_in[23];
    const float* c2_wc    = (const float*)d_in[24];
    const float* c2_bc    = (const float*)d_in[25];

    float *p_h, *p_w1, *p_w2, *p_ws;
    cudaGetSymbolAddress((void**)&p_h,  g_h);
    cudaGetSymbolAddress((void**)&p_w1, g_wc1);
    cudaGetSymbolAddress((void**)&p_w2, g_wc2);
    cudaGetSymbolAddress((void**)&p_ws, g_wskip);

    cudaFuncSetAttribute((const void*)conv3d_kernel<32,96,94,false>,
                         cudaFuncAttributeMaxDynamicSharedMemorySize, SMEM_BYTES);
    cudaFuncSetAttribute((const void*)conv3d_kernel<64,94,92,true>,
                         cudaFuncAttributeMaxDynamicSharedMemorySize, SMEM_BYTES);

    // style MLPs + modulated/demodulated weights
    prep_kernel<<<2, 256>>>(s, skip_w1, skip_b1, skip_w2, skip_b2, skip_w3, skip_b3,
                            skip_wc, p_ws, 64, 64, 32, 1);
    prep_kernel<<<2, 256>>>(s, c1_w1, c1_b1, c1_w2, c1_b2, c1_w3, c1_b3,
                            c1_wc, p_w1, 64, 64, 32, 27);
    prep_kernel<<<2, 256>>>(s, c2_w1, c2_b1, c2_w2, c2_b2, c2_w3, c2_b3,
                            c2_wc, p_w2, 128, 128, 64, 27);

    // c1: x -> h (leaky applied)
    conv3d_kernel<32,96,94,false><<<dim3(6,24,48), 256, SMEM_BYTES>>>(
        x, p_w1, c1_bc, nullptr, nullptr, nullptr, p_h);

    // c2 + fused skip + biases + final leaky -> out
    conv3d_kernel<64,94,92,true><<<dim3(6,23,46), 256, SMEM_BYTES>>>(
        p_h, p_w2, c2_bc, x, p_ws, skip_bc, (float*)d_out);
}

// round 2
// speedup vs baseline: 1.0501x; 1.0501x over previous
#include <cuda_runtime.h>

typedef unsigned long long ull;

__device__ __forceinline__ ull pack2(float lo, float hi){
    ull r; asm("mov.b64 %0, {%1, %2};" : "=l"(r) : "f"(lo), "f"(hi)); return r;
}
__device__ __forceinline__ void unpack2(ull v, float& lo, float& hi){
    asm("mov.b64 {%0, %1}, %2;" : "=f"(lo), "=f"(hi) : "l"(v));
}
__device__ __forceinline__ void fma2(ull& acc, ull a, ull b){
    asm("fma.rn.f32x2 %0, %1, %2, %0;" : "+l"(acc) : "l"(a), "l"(b));
}
__device__ __forceinline__ float leaky(float v){ return v > 0.f ? v : 0.01f*v; }

// ---------------- scratch (device globals; no runtime allocation) ----------------
__device__ float g_h[(size_t)2*64*94*94*94];   // c1 output (after leaky), 425 MB
__device__ float g_wc1[2*32*27*64];            // modulated c1 weights  [n][i][k][o]
__device__ float g_wc2[2*64*27*64];            // modulated c2 weights  [n][i][k][o]
__device__ float g_wskip[2*32*64];             // modulated skip weights [n][i][o]

// ---------------- prep: style MLP + weight modulation/demodulation ----------------
__global__ void prep_kernel(const float* __restrict__ s,
                            const float* __restrict__ w1, const float* __restrict__ b1,
                            const float* __restrict__ w2, const float* __restrict__ b2,
                            const float* __restrict__ w3, const float* __restrict__ b3,
                            const float* __restrict__ wc,
                            float* __restrict__ gw,
                            int H1, int H2, int ICn, int Kn)
{
    const int n   = blockIdx.x;
    const int tid = threadIdx.x;
    __shared__ float sv[64], a1[128], a2[128], mod[64], dem[64];
    if (tid < 64) sv[tid] = s[n*64 + tid];
    __syncthreads();
    if (tid < H1){
        float acc = b1[tid];
        for (int k = 0; k < 64; k++) acc += sv[k]*w1[tid*64 + k];
        a1[tid] = leaky(acc);
    }
    __syncthreads();
    if (tid < H2){
        float acc = b2[tid];
        for (int k = 0; k < H1; k++) acc += a1[k]*w2[tid*H1 + k];
        a2[tid] = leaky(acc);
    }
    __syncthreads();
    if (tid < ICn){
        float acc = b3[tid];
        for (int k = 0; k < H2; k++) acc += a2[k]*w3[tid*H2 + k];
        mod[tid] = acc;
    }
    __syncthreads();
    if (tid < 64){                 // per output channel: demod scalar
        float ssum = 0.f;
        for (int i = 0; i < ICn; i++){
            float m = mod[i];
            const float* wp = wc + (tid*ICn + i)*Kn;
            for (int k = 0; k < Kn; k++){ float t = wp[k]*m; ssum += t*t; }
        }
        dem[tid] = rsqrtf(ssum + 1e-8f);
    }
    __syncthreads();
    const int total = ICn*Kn*64;
    for (int e = tid; e < total; e += blockDim.x){
        int o = e & 63;
        int r = e >> 6;
        int k = r % Kn;
        int i = r / Kn;
        gw[n*total + e] = wc[(o*ICn + i)*Kn + k] * mod[i] * dem[o];
    }
}

// ---------------- output store helper ----------------
template<int OUTD>
__device__ __forceinline__ void store_row(float* __restrict__ out, int n, int oc,
                                          int oz, int oy, int gx0, const float* v)
{
    int base = ((n*64 + oc)*OUTD + oz)*OUTD*OUTD + oy*OUTD + gx0;
    if constexpr ((OUTD & 3) == 0){
        #pragma unroll
        for (int g = 0; g < 2; g++){
            if (gx0 + 4*g + 3 < OUTD)
                *(float4*)(out + base + 4*g) = make_float4(v[4*g], v[4*g+1], v[4*g+2], v[4*g+3]);
        }
    } else {
        #pragma unroll
        for (int g = 0; g < 4; g++){
            int xs = gx0 + 2*g;
            if (xs + 1 < OUTD)
                *(float2*)(out + base + 2*g) = make_float2(v[2*g], v[2*g+1]);
            else if (xs < OUTD)
                out[base + 2*g] = v[2*g];
        }
    }
}

// ---------------- direct 3x3x3 conv, packed f32x2 micro-kernel ----------------
// CTA: 64 oc x (4z x 4y x 16x) voxels, 256 threads.
// Thread: 8 oc (4 f32x2 pairs) x 8 consecutive-x voxels = 32 ull accumulators.
// Smem per ic-chunk(8): input halo tile [8][6][6][20] + weights [8][27][64].
template<int IC, int IND, int OUTD, bool FUSE_SKIP>
__global__ __launch_bounds__(256, 2)
void conv3d_kernel(const float* __restrict__ in,     // [2][IC][IND^3]
                   const float* __restrict__ wbuf,   // [2][IC][27][64]
                   const float* __restrict__ bias1,  // [64]
                   const float* __restrict__ xsrc,   // x, for fused skip
                   const float* __restrict__ wskip,  // [2][32][64]
                   const float* __restrict__ bias2,  // skip bias
                   float* __restrict__ out)          // [2][64][OUTD^3]
{
    constexpr int BZ = (OUTD + 3) / 4;
    extern __shared__ float smem[];
    float* s_in = smem;           // 8*6*6*20 = 5760 floats
    float* s_w  = smem + 5760;    // 8*27*64 = 13824 floats

    const int tid = threadIdx.x;
    const int ocg = tid & 7;          // 0..7 -> oc base
    const int vg  = tid >> 3;         // 0..31
    const int tz  = vg >> 3;          // 0..3
    const int ty  = (vg >> 1) & 3;    // 0..3
    const int xb  = (vg & 1) * 8;     // 0 or 8
    const int ob  = ocg * 8;

    const int bx = blockIdx.x, by = blockIdx.y;
    const int n  = blockIdx.z / BZ;
    const int bz = blockIdx.z % BZ;
    const int z0 = bz*4, y0 = by*4, x0c = bx*16;

    const float* inb = in + (size_t)n * IC * IND * IND * IND;

    ull acc[4][8];
    #pragma unroll
    for (int p = 0; p < 4; p++)
        #pragma unroll
        for (int v = 0; v < 8; v++) acc[p][v] = 0ull;

    #pragma unroll 1
    for (int ic0 = 0; ic0 < IC; ic0 += 8){
        __syncthreads();
        // cooperative load: input halo tile (zero-fill out of range)
        #pragma unroll 1
        for (int e = tid; e < 8*6*6*18; e += 256){
            int xx = e % 18; int t = e / 18;
            int yy = t % 6;  t /= 6;
            int zz = t % 6;  int ic = t / 6;
            int gz = z0 + zz, gy = y0 + yy, gx = x0c + xx;
            float v = 0.f;
            if (gz < IND && gy < IND && gx < IND)
                v = inb[((ic0 + ic)*IND + gz)*(IND*IND) + gy*IND + gx];
            s_in[((ic*6 + zz)*6 + yy)*20 + xx] = v;
        }
        // cooperative load: weight chunk (contiguous)
        {
            const float4* wsrc = (const float4*)(wbuf + ((size_t)n*IC + ic0)*27*64);
            float4* wdst = (float4*)s_w;
            #pragma unroll 1
            for (int e = tid; e < 8*27*16; e += 256) wdst[e] = wsrc[e];
        }
        __syncthreads();

        #pragma unroll 1
        for (int ic = 0; ic < 8; ic++){
            #pragma unroll
            for (int kz = 0; kz < 3; kz++){
                #pragma unroll
                for (int ky = 0; ky < 3; ky++){
                    const float* r = s_in + ((ic*6 + tz + kz)*6 + (ty + ky))*20 + xb;
                    float4 ra = *(const float4*)r;
                    float4 rb = *(const float4*)(r + 4);
                    float2 rc = *(const float2*)(r + 8);
                    ull dup[10];
                    dup[0] = pack2(ra.x, ra.x); dup[1] = pack2(ra.y, ra.y);
                    dup[2] = pack2(ra.z, ra.z); dup[3] = pack2(ra.w, ra.w);
                    dup[4] = pack2(rb.x, rb.x); dup[5] = pack2(rb.y, rb.y);
                    dup[6] = pack2(rb.z, rb.z); dup[7] = pack2(rb.w, rb.w);
                    dup[8] = pack2(rc.x, rc.x); dup[9] = pack2(rc.y, rc.y);
                    const float* wrow = s_w + ((ic*9 + kz*3 + ky)*3)*64 + ob;
                    #pragma unroll
                    for (int kx = 0; kx < 3; kx++){
                        const ull* wp = (const ull*)(wrow + kx*64);   // pairs (2o,2o+1), 8B aligned
                        ull w0 = wp[0], w1 = wp[1], w2 = wp[2], w3 = wp[3];
                        #pragma unroll
                        for (int v = 0; v < 8; v++){
                            ull d = dup[v + kx];
                            fma2(acc[0][v], w0, d);
                            fma2(acc[1][v], w1, d);
                            fma2(acc[2][v], w2, d);
                            fma2(acc[3][v], w3, d);
                        }
                    }
                }
            }
        }
    }

    if constexpr (FUSE_SKIP){
        // fused 1x1 skip conv on x at cropped coords (+2 offset)
        float* s_xs = smem;          // [32][4][4][16] = 8192 floats
        float* s_ws = smem + 8192;   // [32][64]       = 2048 floats
        __syncthreads();
        const float* xbatch = xsrc + (size_t)n * 32 * 96 * 96 * 96;
        #pragma unroll 1
        for (int e = tid; e < 8192; e += 256){
            int xx = e & 15, yy = (e >> 4) & 3, zz = (e >> 6) & 3, ic = e >> 8;
            int gz = z0 + 2 + zz, gy = y0 + 2 + yy, gx = x0c + 2 + xx;
            float v = 0.f;
            if (gz < 96 && gy < 96 && gx < 96)
                v = xbatch[(ic*96 + gz)*9216 + gy*96 + gx];
            s_xs[e] = v;
        }
        #pragma unroll 1
        for (int e = tid; e < 2048; e += 256)
            s_ws[e] = wskip[n*2048 + e];
        __syncthreads();

        #pragma unroll 1
        for (int ic = 0; ic < 32; ic++){
            const ull* wp = (const ull*)(s_ws + ic*64 + ob);
            ull w0 = wp[0], w1 = wp[1], w2 = wp[2], w3 = wp[3];
            const float* xr = s_xs + ic*256 + (tz*4 + ty)*16 + xb;
            float4 xa = *(const float4*)xr;
            float4 xv = *(const float4*)(xr + 4);
            float xin[8] = {xa.x, xa.y, xa.z, xa.w, xv.x, xv.y, xv.z, xv.w};
            #pragma unroll
            for (int v = 0; v < 8; v++){
                ull d = pack2(xin[v], xin[v]);
                fma2(acc[0][v], w0, d);
                fma2(acc[1][v], w1, d);
                fma2(acc[2][v], w2, d);
                fma2(acc[3][v], w3, d);
            }
        }
    }

    // epilogue: bias (+skip bias), leaky, vectorized store
    const int oz = z0 + tz, oy = y0 + ty;
    if (oz < OUTD && oy < OUTD){
        const int gx0 = x0c + xb;
        #pragma unroll
        for (int p = 0; p < 4; p++){
            const int oc0 = ob + 2*p;
            float b0 = bias1[oc0],     b1v = bias1[oc0 + 1];
            if constexpr (FUSE_SKIP){ b0 += bias2[oc0]; b1v += bias2[oc0 + 1]; }
            float lo[8], hi[8];
            #pragma unroll
            for (int v = 0; v < 8; v++){
                float a, b;
                unpack2(acc[p][v], a, b);
                lo[v] = leaky(a + b0);
                hi[v] = leaky(b + b1v);
            }
            store_row<OUTD>(out, n, oc0,     oz, oy, gx0, lo);
            store_row<OUTD>(out, n, oc0 + 1, oz, oy, gx0, hi);
        }
    }
}

// ---------------- launch ----------------
static const int SMEM_BYTES = (5760 + 13824) * 4;   // 78336

extern "C" void kernel_launch(void* const* d_in, const int* in_sizes, int n_in,
                              void* d_out, int out_size)
{
    (void)in_sizes; (void)n_in; (void)out_size;

    const float* x        = (const float*)d_in[0];
    const float* s        = (const float*)d_in[1];
    const float* skip_w1  = (const float*)d_in[2];
    const float* skip_b1  = (const float*)d_in[3];
    const float* skip_w2  = (const float*)d_in[4];
    const float* skip_b2  = (const float*)d_in[5];
    const float* skip_w3  = (const float*)d_in[6];
    const float* skip_b3  = (const float*)d_in[7];
    const float* skip_wc  = (const float*)d_in[8];
    const float* skip_bc  = (const float*)d_in[9];
    const float* c1_w1    = (const float*)d_in[10];
    const float* c1_b1    = (const float*)d_in[11];
    const float* c1_w2    = (const float*)d_in[12];
    const float* c1_b2    = (const float*)d_in[13];
    const float* c1_w3    = (const float*)d_in[14];
    const float* c1_b3    = (const float*)d_in[15];
    const float* c1_wc    = (const float*)d_in[16];
    const float* c1_bc    = (const float*)d_in[17];
    const float* c2_w1    = (const float*)d_in[18];
    const float* c2_b1    = (const float*)d_in[19];
    const float* c2_w2    = (const float*)d_in[20];
    const float* c2_b2    = (const float*)d_in[21];
    const float* c2_w3    = (const float*)d_in[22];
    const float* c2_b3    = (const float*)d_in[23];
    const float* c2_wc    = (const float*)d_in[24];
    const float* c2_bc    = (const float*)d_in[25];

    float *p_h, *p_w1, *p_w2, *p_ws;
    cudaGetSymbolAddress((void**)&p_h,  g_h);
    cudaGetSymbolAddress((void**)&p_w1, g_wc1);
    cudaGetSymbolAddress((void**)&p_w2, g_wc2);
    cudaGetSymbolAddress((void**)&p_ws, g_wskip);

    cudaFuncSetAttribute((const void*)conv3d_kernel<32,96,94,false>,
                         cudaFuncAttributeMaxDynamicSharedMemorySize, SMEM_BYTES);
    cudaFuncSetAttribute((const void*)conv3d_kernel<64,94,92,true>,
                         cudaFuncAttributeMaxDynamicSharedMemorySize, SMEM_BYTES);

    // style MLPs + modulated/demodulated weights
    prep_kernel<<<2, 256>>>(s, skip_w1, skip_b1, skip_w2, skip_b2, skip_w3, skip_b3,
                            skip_wc, p_ws, 64, 64, 32, 1);
    prep_kernel<<<2, 256>>>(s, c1_w1, c1_b1, c1_w2, c1_b2, c1_w3, c1_b3,
                            c1_wc, p_w1, 64, 64, 32, 27);
    prep_kernel<<<2, 256>>>(s, c2_w1, c2_b1, c2_w2, c2_b2, c2_w3, c2_b3,
                            c2_wc, p_w2, 128, 128, 64, 27);

    // c1: x -> h (leaky applied)
    conv3d_kernel<32,96,94,false><<<dim3(6,24,48), 256, SMEM_BYTES>>>(
        x, p_w1, c1_bc, nullptr, nullptr, nullptr, p_h);

    // c2 + fused skip + biases + final leaky -> out
    conv3d_kernel<64,94,92,true><<<dim3(6,23,46), 256, SMEM_BYTES>>>(
        p_h, p_w2, c2_bc, x, p_ws, skip_bc, (float*)d_out);
}